// round 6
// baseline (speedup 1.0000x reference)
#include <cuda_runtime.h>
#include <cuda_fp16.h>
#include <cstddef>

// ---------------------------------------------------------------------------
// GMM (MoNet) graph conv, transform-then-gather, fp16 k-interleaved y:
//   T: y[m, hp, {k0,k1,k2,pad}] = sum_f x[m,f] * W[k,f,2hp..]   (ffma2 GEMM)
//   G: out[n,h] = sum_e sum_k gauss[e,k] * y[col_e, ...]        (1 LDG.128/edge)
// Row layout: H/2 chunks of 16B ({half2 k0, half2 k1, half2 k2, pad}).
// G1 row = 256B (2 lines), G2 row = 128B (1 line, fully coalesced per node).
// ---------------------------------------------------------------------------

#define MAXN 131072
__device__ __half g_y1[MAXN * 128];  // [N][16 chunks][8 halves]  32MB region
__device__ float  g_h [MAXN * 32];   // layer1 out f32
__device__ __half g_y2[MAXN * 64];   // [N][8 chunks][8 halves]

typedef unsigned long long ull;

__device__ __forceinline__ ull pk2(float x, float y) {
    ull r; asm("mov.b64 %0, {%1,%2};" : "=l"(r) : "f"(x), "f"(y)); return r;
}
__device__ __forceinline__ void upk2(ull v, float& x, float& y) {
    asm("mov.b64 {%0,%1}, %2;" : "=f"(x), "=f"(y) : "l"(v));
}
__device__ __forceinline__ void ffma2(ull& d, ull a, ull b) {
    asm("fma.rn.f32x2 %0, %1, %2, %0;" : "+l"(d) : "l"(a), "l"(b));
}

// ======================= transform (tiled GEMM, half2 out) =================
// Output chunk layout: half2 index = hp*4 + k, row stride RSTR2 = 4*(H/2).
template<int KD, int H>
__global__ void __launch_bounds__(192)
transform_kernel(const float* __restrict__ X, const float* __restrict__ W,
                 __half2* __restrict__ Y, int n_nodes)
{
    constexpr int NCOL = 3 * H;
    constexpr int NC2  = NCOL / 2;         // 48 (T1) or 24 (T2) logical pairs
    constexpr int NT   = NC2 / 12;         // 4 (T1) or 2 (T2)
    constexpr int H2   = H / 2;
    constexpr int RSTR2 = 4 * H2;          // half2 per row (incl. pad)
    constexpr int MT   = 128;
    constexpr int XSTR = MT + 2;

    extern __shared__ float smem[];
    float* Xs = smem;                      // [KD][XSTR]
    float* Ws = smem + KD * XSTR;          // [KD][NCOL]

    const int tid = threadIdx.x;
    const int mt0 = blockIdx.x * MT;

    for (int i = tid; i < KD * NCOL; i += 192) {
        int f = i / NCOL, n = i % NCOL;
        int k = n / H, h = n % H;
        Ws[f * NCOL + n] = W[((size_t)k * KD + f) * H + h];
    }
    for (int i = tid; i < MT * KD; i += 192) {
        int m = i / KD, f = i % KD;
        float v = 0.f;
        if (mt0 + m < n_nodes) v = X[(size_t)(mt0 + m) * KD + f];
        Xs[f * XSTR + m] = v;
    }
    __syncthreads();

    const int tx = tid % 12;
    const int ty = tid / 12;               // 0..15
    const int m0 = ty * 8;

    ull acc[8][NT];
    #pragma unroll
    for (int i = 0; i < 8; i++)
        #pragma unroll
        for (int s = 0; s < NT; s++) acc[i][s] = 0ull;

    for (int f = 0; f < KD; f++) {
        float xm[8];
        #pragma unroll
        for (int i = 0; i < 4; i++) {
            const ull xp = *(const ull*)&Xs[f * XSTR + m0 + 2 * i];
            upk2(xp, xm[2 * i], xm[2 * i + 1]);
        }
        #pragma unroll
        for (int s = 0; s < NT; s++) {
            const ull wp = *(const ull*)&Ws[f * NCOL + 2 * (tx + 12 * s)];
            #pragma unroll
            for (int i = 0; i < 8; i++)
                ffma2(acc[i][s], pk2(xm[i], xm[i]), wp);
        }
    }

    #pragma unroll
    for (int i = 0; i < 8; i++) {
        const int m = mt0 + m0 + i;
        if (m >= n_nodes) break;
        #pragma unroll
        for (int s = 0; s < NT; s++) {
            float v0, v1; upk2(acc[i][s], v0, v1);
            const int j  = tx + 12 * s;       // logical pair: k = j/H2, hp = j%H2
            const int k  = j / H2;
            const int hp = j % H2;
            Y[(size_t)m * RSTR2 + hp * 4 + k] = __floats2half2_rn(v0, v1);
        }
    }
}

// ========================= gather kernels ==================================
#define LOAD_GAUSS_PARAMS()                                                   \
    const float m0_ = mu[0], m1_ = mu[1], m2_ = mu[2],                        \
                m3_ = mu[3], m4_ = mu[4], m5_ = mu[5];                        \
    float s_;                                                                 \
    s_ = sigma[0]; const float i0_ = 1.f/(s_*s_);                             \
    s_ = sigma[1]; const float i1_ = 1.f/(s_*s_);                             \
    s_ = sigma[2]; const float i2_ = 1.f/(s_*s_);                             \
    s_ = sigma[3]; const float i3_ = 1.f/(s_*s_);                             \
    s_ = sigma[4]; const float i4_ = 1.f/(s_*s_);                             \
    s_ = sigma[5]; const float i5_ = 1.f/(s_*s_);

#define GAUSS3(pv, g0, g1, g2) do {                                           \
    float dx_, dy_, q_;                                                       \
    dx_ = (pv).x - m0_; dy_ = (pv).y - m1_;                                   \
    q_ = dx_*dx_*i0_ + dy_*dy_*i1_; g0 = __expf(-0.5f * q_);                  \
    dx_ = (pv).x - m2_; dy_ = (pv).y - m3_;                                   \
    q_ = dx_*dx_*i2_ + dy_*dy_*i3_; g1 = __expf(-0.5f * q_);                  \
    dx_ = (pv).x - m4_; dy_ = (pv).y - m5_;                                   \
    q_ = dx_*dx_*i4_ + dy_*dy_*i5_; g2 = __expf(-0.5f * q_);                  \
} while (0)

// LPN lanes per node; lane owns one 16B chunk {k0,k1,k2,pad}: 1 LDG.128/edge.
template<int NWARP, int H, int LPN>
__global__ void __launch_bounds__(NWARP * 32)
gather_kernel(const int* __restrict__ row_ptr, const int* __restrict__ col_idx,
              const float2* __restrict__ p,
              const float* __restrict__ mu, const float* __restrict__ sigma,
              const uint4* __restrict__ y,     // [N][H2] 16B chunks
              float* __restrict__ out,         // [N, H]  f32
              int n_nodes)
{
    constexpr int GRP = 4, CAP = GRP * 16;
    constexpr int H2  = H / 2;               // chunks per row
    constexpr int NPN = 32 / LPN;            // nodes per warp pass

    __shared__ float4 stg[NWARP][CAP];

    const int lane = threadIdx.x & 31;
    const int wid  = threadIdx.x >> 5;
    const int s    = lane / LPN;             // node slot within pass
    const int hl   = lane % LPN;             // chunk index
    const int base = (blockIdx.x * NWARP + wid) * GRP;
    if (base >= n_nodes) return;

    LOAD_GAUSS_PARAMS();

    const int ng   = min(GRP, n_nodes - base);
    const int e0   = row_ptr[base];
    const int ecnt = row_ptr[base + ng] - e0;
    const bool fast = (ecnt <= CAP);

    if (fast) {
        for (int j = lane; j < ecnt; j += 32) {
            const int e = e0 + j;
            const int c = col_idx[e];
            const float2 pv = __ldg(p + e);
            float g0, g1, g2; GAUSS3(pv, g0, g1, g2);
            stg[wid][j] = make_float4(g0, g1, g2, __int_as_float(c));
        }
    }
    __syncwarp();

    #pragma unroll
    for (int pi = 0; pi < GRP / NPN; pi++) {
        const int n = base + pi * NPN + s;
        const bool valid = (n < n_nodes);
        const int nc  = valid ? n : base;
        const int st  = __ldg(row_ptr + nc);
        const int deg = valid ? (__ldg(row_ptr + nc + 1) - st) : 0;

        ull a0 = 0ull, a1 = 0ull, a2 = 0ull;

        if (fast) {
            const float4* sd = &stg[wid][st - e0];
            const bool u16 = __all_sync(0xffffffffu, deg == 16);
            #define G_BODY(J) do {                                            \
                const float4 ed = sd[(J)];                                    \
                const int c = __float_as_int(ed.w);                           \
                const uint4 v = __ldg(y + (size_t)c * H2 + hl);               \
                const float2 f0 = __half22float2(*(const __half2*)&v.x);      \
                const float2 f1 = __half22float2(*(const __half2*)&v.y);      \
                const float2 f2 = __half22float2(*(const __half2*)&v.z);      \
                ffma2(a0, pk2(ed.x, ed.x), pk2(f0.x, f0.y));                  \
                ffma2(a1, pk2(ed.y, ed.y), pk2(f1.x, f1.y));                  \
                ffma2(a2, pk2(ed.z, ed.z), pk2(f2.x, f2.y));                  \
            } while (0)
            if (u16) {
                #pragma unroll
                for (int j = 0; j < 16; j++) G_BODY(j);
            } else {
                const int maxd = __reduce_max_sync(0xffffffffu, deg);
                for (int j = 0; j < maxd; j++)
                    if (j < deg) G_BODY(j);
            }
            #undef G_BODY
        } else {
            const int maxd = __reduce_max_sync(0xffffffffu, deg);
            for (int j = 0; j < maxd; j++) {
                if (j < deg) {
                    const int e = st + j;
                    const int c = __ldg(col_idx + e);
                    const float2 pv = __ldg(p + e);
                    float g0, g1, g2; GAUSS3(pv, g0, g1, g2);
                    const uint4 v = __ldg(y + (size_t)c * H2 + hl);
                    const float2 f0 = __half22float2(*(const __half2*)&v.x);
                    const float2 f1 = __half22float2(*(const __half2*)&v.y);
                    const float2 f2 = __half22float2(*(const __half2*)&v.z);
                    ffma2(a0, pk2(g0, g0), pk2(f0.x, f0.y));
                    ffma2(a1, pk2(g1, g1), pk2(f1.x, f1.y));
                    ffma2(a2, pk2(g2, g2), pk2(f2.x, f2.y));
                }
            }
        }

        if (valid) {
            float x0, x1, y0v, y1v, z0, z1;
            upk2(a0, x0, x1); upk2(a1, y0v, y1v); upk2(a2, z0, z1);
            float2 o = make_float2(x0 + y0v + z0, x1 + y1v + z1);
            *(float2*)(out + (size_t)n * H + 2 * hl) = o;
        }
    }
}

// =============================== launch ====================================
extern "C" void kernel_launch(void* const* d_in, const int* in_sizes, int n_in,
                              void* d_out, int out_size)
{
    const int*    row_ptr = (const int*)d_in[0];    // int32 (JAX x64 disabled)
    const int*    col_idx = (const int*)d_in[1];
    const float*  x       = (const float*)d_in[2];
    const float2* p       = (const float2*)d_in[3];
    const float*  mu      = (const float*)d_in[4];
    const float*  sg      = (const float*)d_in[5];
    const float*  W1      = (const float*)d_in[6];
    const float*  W2      = (const float*)d_in[7];

    const int n_nodes = in_sizes[0] - 1;

    void *y1p, *y2p; float* hp;
    cudaGetSymbolAddress(&y1p, g_y1);
    cudaGetSymbolAddress((void**)&hp, g_h);
    cudaGetSymbolAddress(&y2p, g_y2);

    constexpr int NWARP = 8;
    const int gblocks = (n_nodes + NWARP * 4 - 1) / (NWARP * 4);
    const int tblocks = (n_nodes + 127) / 128;

    constexpr size_t smem_t1 = (64 * 130 + 64 * 96) * sizeof(float);  // 57.9KB
    constexpr size_t smem_t2 = (32 * 130 + 32 * 48) * sizeof(float);  // 22.8KB

    cudaFuncSetAttribute(transform_kernel<64, 32>,
                         cudaFuncAttributeMaxDynamicSharedMemorySize, (int)smem_t1);
    cudaFuncSetAttribute(transform_kernel<32, 16>,
                         cudaFuncAttributeMaxDynamicSharedMemorySize, (int)smem_t2);

    // T1: y1 = x * W1  (fp16 k-interleaved, 256B rows)
    transform_kernel<64, 32><<<tblocks, 192, smem_t1>>>(x, W1, (__half2*)y1p, n_nodes);
    // G1: h = gather(y1)  (H=32, 16 lanes/node, 1 LDG.128/edge)
    gather_kernel<NWARP, 32, 16><<<gblocks, NWARP * 32>>>(
        row_ptr, col_idx, p, mu, sg, (const uint4*)y1p, hp, n_nodes);
    // T2: y2 = h * W2  (fp16 k-interleaved, 128B rows)
    transform_kernel<32, 16><<<tblocks, 192, smem_t2>>>(hp, W2, (__half2*)y2p, n_nodes);
    // G2: out = gather(y2)  (H=16, 8 lanes/node, 1 LDG.128/edge, 1 line/node)
    gather_kernel<NWARP, 16, 8><<<gblocks, NWARP * 32>>>(
        row_ptr, col_idx, p, mu, sg, (const uint4*)y2p, (float*)d_out, n_nodes);
}

// round 7
// speedup vs baseline: 1.1036x; 1.1036x over previous
#include <cuda_runtime.h>
#include <cuda_fp16.h>
#include <cstddef>

// ---------------------------------------------------------------------------
// GMM (MoNet) graph conv, transform-then-gather, fp16 intermediates.
//   T1: y1[m][k][h] fp16, unpadded rows of 192B ([3][16] half2)
//   G1: H=32, 8 lanes/node, 3x LDG.64 (uint2) per lane per edge
//   T2: y2[m][hp][{k0,k1,k2,pad}] padded 128B rows
//   G2: H=16, 8 lanes/node, 1x LDG.128 per lane per edge (1 line/node)
// ---------------------------------------------------------------------------

#define MAXN 131072
__device__ __half g_y1[MAXN * 96];   // [N][3][32]  unpadded, 192B rows
__device__ float  g_h [MAXN * 32];   // layer1 out f32
__device__ __half g_y2[MAXN * 64];   // [N][8 chunks][8 halves] padded 128B rows

typedef unsigned long long ull;

__device__ __forceinline__ ull pk2(float x, float y) {
    ull r; asm("mov.b64 %0, {%1,%2};" : "=l"(r) : "f"(x), "f"(y)); return r;
}
__device__ __forceinline__ void upk2(ull v, float& x, float& y) {
    asm("mov.b64 {%0,%1}, %2;" : "=f"(x), "=f"(y) : "l"(v));
}
__device__ __forceinline__ void ffma2(ull& d, ull a, ull b) {
    asm("fma.rn.f32x2 %0, %1, %2, %0;" : "+l"(d) : "l"(a), "l"(b));
}

// ======================= transforms (tiled ffma2 GEMM) =====================
// PAD=0: half2 index = m*NC2 + k*H2 + hp  (unpadded, T1)
// PAD=1: half2 index = m*4*H2 + hp*4 + k  (16B k-chunks, T2)
template<int KD, int H, int PAD>
__global__ void __launch_bounds__(192)
transform_kernel(const float* __restrict__ X, const float* __restrict__ W,
                 __half2* __restrict__ Y, int n_nodes)
{
    constexpr int NCOL = 3 * H;
    constexpr int NC2  = NCOL / 2;
    constexpr int NT   = NC2 / 12;
    constexpr int H2   = H / 2;
    constexpr int RSTR2 = PAD ? 4 * H2 : NC2;
    constexpr int MT   = 128;
    constexpr int XSTR = MT + 2;

    extern __shared__ float smem[];
    float* Xs = smem;                      // [KD][XSTR]
    float* Ws = smem + KD * XSTR;          // [KD][NCOL]

    const int tid = threadIdx.x;
    const int mt0 = blockIdx.x * MT;

    for (int i = tid; i < KD * NCOL; i += 192) {
        int f = i / NCOL, n = i % NCOL;
        int k = n / H, h = n % H;
        Ws[f * NCOL + n] = W[((size_t)k * KD + f) * H + h];
    }
    for (int i = tid; i < MT * KD; i += 192) {
        int m = i / KD, f = i % KD;
        float v = 0.f;
        if (mt0 + m < n_nodes) v = X[(size_t)(mt0 + m) * KD + f];
        Xs[f * XSTR + m] = v;
    }
    __syncthreads();

    const int tx = tid % 12;
    const int ty = tid / 12;               // 0..15
    const int m0 = ty * 8;

    ull acc[8][NT];
    #pragma unroll
    for (int i = 0; i < 8; i++)
        #pragma unroll
        for (int s = 0; s < NT; s++) acc[i][s] = 0ull;

    for (int f = 0; f < KD; f++) {
        float xm[8];
        #pragma unroll
        for (int i = 0; i < 4; i++) {
            const ull xp = *(const ull*)&Xs[f * XSTR + m0 + 2 * i];
            upk2(xp, xm[2 * i], xm[2 * i + 1]);
        }
        #pragma unroll
        for (int s = 0; s < NT; s++) {
            const ull wp = *(const ull*)&Ws[f * NCOL + 2 * (tx + 12 * s)];
            #pragma unroll
            for (int i = 0; i < 8; i++)
                ffma2(acc[i][s], pk2(xm[i], xm[i]), wp);
        }
    }

    #pragma unroll
    for (int i = 0; i < 8; i++) {
        const int m = mt0 + m0 + i;
        if (m >= n_nodes) break;
        #pragma unroll
        for (int s = 0; s < NT; s++) {
            float v0, v1; upk2(acc[i][s], v0, v1);
            const int j  = tx + 12 * s;       // logical pair: k = j/H2, hp = j%H2
            const int k  = j / H2;
            const int hp = j % H2;
            const int idx = PAD ? (hp * 4 + k) : (k * H2 + hp);
            Y[(size_t)m * RSTR2 + idx] = __floats2half2_rn(v0, v1);
        }
    }
}

// ========================= gather kernels ==================================
#define LOAD_GAUSS_PARAMS()                                                   \
    const float m0_ = mu[0], m1_ = mu[1], m2_ = mu[2],                        \
                m3_ = mu[3], m4_ = mu[4], m5_ = mu[5];                        \
    float s_;                                                                 \
    s_ = sigma[0]; const float i0_ = 1.f/(s_*s_);                             \
    s_ = sigma[1]; const float i1_ = 1.f/(s_*s_);                             \
    s_ = sigma[2]; const float i2_ = 1.f/(s_*s_);                             \
    s_ = sigma[3]; const float i3_ = 1.f/(s_*s_);                             \
    s_ = sigma[4]; const float i4_ = 1.f/(s_*s_);                             \
    s_ = sigma[5]; const float i5_ = 1.f/(s_*s_);

#define GAUSS3(pv, g0, g1, g2) do {                                           \
    float dx_, dy_, q_;                                                       \
    dx_ = (pv).x - m0_; dy_ = (pv).y - m1_;                                   \
    q_ = dx_*dx_*i0_ + dy_*dy_*i1_; g0 = __expf(-0.5f * q_);                  \
    dx_ = (pv).x - m2_; dy_ = (pv).y - m3_;                                   \
    q_ = dx_*dx_*i2_ + dy_*dy_*i3_; g1 = __expf(-0.5f * q_);                  \
    dx_ = (pv).x - m4_; dy_ = (pv).y - m5_;                                   \
    q_ = dx_*dx_*i4_ + dy_*dy_*i5_; g2 = __expf(-0.5f * q_);                  \
} while (0)

// ---- G1: H=32, unpadded [3][16]half2 rows (24 uint2). 8 lanes/node, -------
// ---- each lane: 3x LDG.64 per edge (uint2 = 2 h-pairs per k). -------------
template<int NWARP, int GRP>
__global__ void __launch_bounds__(NWARP * 32)
gather_h32(const int* __restrict__ row_ptr, const int* __restrict__ col_idx,
           const float2* __restrict__ p,
           const float* __restrict__ mu, const float* __restrict__ sigma,
           const uint2* __restrict__ y,     // [N][24] uint2
           float* __restrict__ out,         // [N][32] f32
           int n_nodes)
{
    constexpr int CAP = GRP * 16;
    __shared__ float4 stg[NWARP][CAP];

    const int lane = threadIdx.x & 31;
    const int wid  = threadIdx.x >> 5;
    const int s    = lane >> 3;              // node slot (4 per pass)
    const int hl   = lane & 7;               // which uint2 pair-group
    const int base = (blockIdx.x * NWARP + wid) * GRP;
    if (base >= n_nodes) return;

    LOAD_GAUSS_PARAMS();

    const int ng   = min(GRP, n_nodes - base);
    const int e0   = row_ptr[base];
    const int ecnt = row_ptr[base + ng] - e0;
    const bool fast = (ecnt <= CAP);

    if (fast) {
        for (int j = lane; j < ecnt; j += 32) {
            const int e = e0 + j;
            const int c = col_idx[e];
            const float2 pv = __ldg(p + e);
            float g0, g1, g2; GAUSS3(pv, g0, g1, g2);
            stg[wid][j] = make_float4(g0, g1, g2, __int_as_float(c));
        }
    }
    __syncwarp();

    #pragma unroll
    for (int pi = 0; pi < GRP / 4; pi++) {
        const int n = base + pi * 4 + s;
        const bool valid = (n < n_nodes);
        const int nc  = valid ? n : base;
        const int st  = __ldg(row_ptr + nc);
        const int deg = valid ? (__ldg(row_ptr + nc + 1) - st) : 0;

        ull a[3][2];
        #pragma unroll
        for (int k = 0; k < 3; k++) { a[k][0] = 0ull; a[k][1] = 0ull; }

        if (fast) {
            const float4* sd = &stg[wid][st - e0];
            const bool u16 = __all_sync(0xffffffffu, deg == 16);
            #define G1_BODY(J) do {                                           \
                const float4 ed = sd[(J)];                                    \
                const int c = __float_as_int(ed.w);                           \
                const uint2* yr = y + (size_t)c * 24 + hl;                    \
                const uint2 v0 = __ldg(yr);                                   \
                const uint2 v1 = __ldg(yr + 8);                               \
                const uint2 v2 = __ldg(yr + 16);                              \
                const float2 c00 = __half22float2(*(const __half2*)&v0.x);    \
                const float2 c01 = __half22float2(*(const __half2*)&v0.y);    \
                const float2 c10 = __half22float2(*(const __half2*)&v1.x);    \
                const float2 c11 = __half22float2(*(const __half2*)&v1.y);    \
                const float2 c20 = __half22float2(*(const __half2*)&v2.x);    \
                const float2 c21 = __half22float2(*(const __half2*)&v2.y);    \
                const ull w0 = pk2(ed.x, ed.x);                               \
                const ull w1 = pk2(ed.y, ed.y);                               \
                const ull w2 = pk2(ed.z, ed.z);                               \
                ffma2(a[0][0], w0, pk2(c00.x, c00.y));                        \
                ffma2(a[0][1], w0, pk2(c01.x, c01.y));                        \
                ffma2(a[1][0], w1, pk2(c10.x, c10.y));                        \
                ffma2(a[1][1], w1, pk2(c11.x, c11.y));                        \
                ffma2(a[2][0], w2, pk2(c20.x, c20.y));                        \
                ffma2(a[2][1], w2, pk2(c21.x, c21.y));                        \
            } while (0)
            if (u16) {
                #pragma unroll
                for (int j = 0; j < 16; j++) G1_BODY(j);
            } else {
                const int maxd = __reduce_max_sync(0xffffffffu, deg);
                for (int j = 0; j < maxd; j++)
                    if (j < deg) G1_BODY(j);
            }
            #undef G1_BODY
        } else {
            const int maxd = __reduce_max_sync(0xffffffffu, deg);
            for (int j = 0; j < maxd; j++) {
                if (j < deg) {
                    const int e = st + j;
                    const int c = __ldg(col_idx + e);
                    const float2 pv = __ldg(p + e);
                    float g0, g1, g2; GAUSS3(pv, g0, g1, g2);
                    const uint2* yr = y + (size_t)c * 24 + hl;
                    const uint2 v0 = __ldg(yr);
                    const uint2 v1 = __ldg(yr + 8);
                    const uint2 v2 = __ldg(yr + 16);
                    const float2 c00 = __half22float2(*(const __half2*)&v0.x);
                    const float2 c01 = __half22float2(*(const __half2*)&v0.y);
                    const float2 c10 = __half22float2(*(const __half2*)&v1.x);
                    const float2 c11 = __half22float2(*(const __half2*)&v1.y);
                    const float2 c20 = __half22float2(*(const __half2*)&v2.x);
                    const float2 c21 = __half22float2(*(const __half2*)&v2.y);
                    ffma2(a[0][0], pk2(g0, g0), pk2(c00.x, c00.y));
                    ffma2(a[0][1], pk2(g0, g0), pk2(c01.x, c01.y));
                    ffma2(a[1][0], pk2(g1, g1), pk2(c10.x, c10.y));
                    ffma2(a[1][1], pk2(g1, g1), pk2(c11.x, c11.y));
                    ffma2(a[2][0], pk2(g2, g2), pk2(c20.x, c20.y));
                    ffma2(a[2][1], pk2(g2, g2), pk2(c21.x, c21.y));
                }
            }
        }

        if (valid) {
            float p00, p01, p10, p11, q00, q01, q10, q11, r00, r01, r10, r11;
            upk2(a[0][0], p00, p01); upk2(a[0][1], p10, p11);
            upk2(a[1][0], q00, q01); upk2(a[1][1], q10, q11);
            upk2(a[2][0], r00, r01); upk2(a[2][1], r10, r11);
            float4 o;
            o.x = p00 + q00 + r00;
            o.y = p01 + q01 + r01;
            o.z = p10 + q10 + r10;
            o.w = p11 + q11 + r11;
            *(float4*)(out + (size_t)n * 32 + 4 * hl) = o;
        }
    }
}

// ---- G2: H=16, padded 128B rows; 8 lanes/node, 1x LDG.128 per edge --------
template<int NWARP, int GRP>
__global__ void __launch_bounds__(NWARP * 32)
gather_h16(const int* __restrict__ row_ptr, const int* __restrict__ col_idx,
           const float2* __restrict__ p,
           const float* __restrict__ mu, const float* __restrict__ sigma,
           const uint4* __restrict__ y,     // [N][8] 16B chunks
           float* __restrict__ out,         // [N][16] f32
           int n_nodes)
{
    constexpr int CAP = GRP * 16;
    __shared__ float4 stg[NWARP][CAP];

    const int lane = threadIdx.x & 31;
    const int wid  = threadIdx.x >> 5;
    const int s    = lane >> 3;              // node slot (4 per pass)
    const int hl   = lane & 7;               // chunk index
    const int base = (blockIdx.x * NWARP + wid) * GRP;
    if (base >= n_nodes) return;

    LOAD_GAUSS_PARAMS();

    const int ng   = min(GRP, n_nodes - base);
    const int e0   = row_ptr[base];
    const int ecnt = row_ptr[base + ng] - e0;
    const bool fast = (ecnt <= CAP);

    if (fast) {
        for (int j = lane; j < ecnt; j += 32) {
            const int e = e0 + j;
            const int c = col_idx[e];
            const float2 pv = __ldg(p + e);
            float g0, g1, g2; GAUSS3(pv, g0, g1, g2);
            stg[wid][j] = make_float4(g0, g1, g2, __int_as_float(c));
        }
    }
    __syncwarp();

    #pragma unroll
    for (int pi = 0; pi < GRP / 4; pi++) {
        const int n = base + pi * 4 + s;
        const bool valid = (n < n_nodes);
        const int nc  = valid ? n : base;
        const int st  = __ldg(row_ptr + nc);
        const int deg = valid ? (__ldg(row_ptr + nc + 1) - st) : 0;

        ull a0 = 0ull, a1 = 0ull, a2 = 0ull;

        if (fast) {
            const float4* sd = &stg[wid][st - e0];
            const bool u16 = __all_sync(0xffffffffu, deg == 16);
            #define G2_BODY(J) do {                                           \
                const float4 ed = sd[(J)];                                    \
                const int c = __float_as_int(ed.w);                           \
                const uint4 v = __ldg(y + (size_t)c * 8 + hl);                \
                const float2 f0 = __half22float2(*(const __half2*)&v.x);      \
                const float2 f1 = __half22float2(*(const __half2*)&v.y);      \
                const float2 f2 = __half22float2(*(const __half2*)&v.z);      \
                ffma2(a0, pk2(ed.x, ed.x), pk2(f0.x, f0.y));                  \
                ffma2(a1, pk2(ed.y, ed.y), pk2(f1.x, f1.y));                  \
                ffma2(a2, pk2(ed.z, ed.z), pk2(f2.x, f2.y));                  \
            } while (0)
            if (u16) {
                #pragma unroll
                for (int j = 0; j < 16; j++) G2_BODY(j);
            } else {
                const int maxd = __reduce_max_sync(0xffffffffu, deg);
                for (int j = 0; j < maxd; j++)
                    if (j < deg) G2_BODY(j);
            }
            #undef G2_BODY
        } else {
            const int maxd = __reduce_max_sync(0xffffffffu, deg);
            for (int j = 0; j < maxd; j++) {
                if (j < deg) {
                    const int e = st + j;
                    const int c = __ldg(col_idx + e);
                    const float2 pv = __ldg(p + e);
                    float g0, g1, g2; GAUSS3(pv, g0, g1, g2);
                    const uint4 v = __ldg(y + (size_t)c * 8 + hl);
                    const float2 f0 = __half22float2(*(const __half2*)&v.x);
                    const float2 f1 = __half22float2(*(const __half2*)&v.y);
                    const float2 f2 = __half22float2(*(const __half2*)&v.z);
                    ffma2(a0, pk2(g0, g0), pk2(f0.x, f0.y));
                    ffma2(a1, pk2(g1, g1), pk2(f1.x, f1.y));
                    ffma2(a2, pk2(g2, g2), pk2(f2.x, f2.y));
                }
            }
        }

        if (valid) {
            float x0, x1, y0v, y1v, z0, z1;
            upk2(a0, x0, x1); upk2(a1, y0v, y1v); upk2(a2, z0, z1);
            float2 o = make_float2(x0 + y0v + z0, x1 + y1v + z1);
            *(float2*)(out + (size_t)n * 16 + 2 * hl) = o;
        }
    }
}

// =============================== launch ====================================
extern "C" void kernel_launch(void* const* d_in, const int* in_sizes, int n_in,
                              void* d_out, int out_size)
{
    const int*    row_ptr = (const int*)d_in[0];    // int32 (JAX x64 disabled)
    const int*    col_idx = (const int*)d_in[1];
    const float*  x       = (const float*)d_in[2];
    const float2* p       = (const float2*)d_in[3];
    const float*  mu      = (const float*)d_in[4];
    const float*  sg      = (const float*)d_in[5];
    const float*  W1      = (const float*)d_in[6];
    const float*  W2      = (const float*)d_in[7];

    const int n_nodes = in_sizes[0] - 1;

    void *y1p, *y2p; float* hp;
    cudaGetSymbolAddress(&y1p, g_y1);
    cudaGetSymbolAddress((void**)&hp, g_h);
    cudaGetSymbolAddress(&y2p, g_y2);

    constexpr int NWARP = 8;
    constexpr int GRP   = 8;
    const int gblocks = (n_nodes + NWARP * GRP - 1) / (NWARP * GRP);
    const int tblocks = (n_nodes + 127) / 128;

    constexpr size_t smem_t1 = (64 * 130 + 64 * 96) * sizeof(float);  // 57.9KB
    constexpr size_t smem_t2 = (32 * 130 + 32 * 48) * sizeof(float);  // 22.8KB

    cudaFuncSetAttribute(transform_kernel<64, 32, 0>,
                         cudaFuncAttributeMaxDynamicSharedMemorySize, (int)smem_t1);
    cudaFuncSetAttribute(transform_kernel<32, 16, 1>,
                         cudaFuncAttributeMaxDynamicSharedMemorySize, (int)smem_t2);

    // T1: y1 = x * W1  (fp16 unpadded [3][16]half2 rows)
    transform_kernel<64, 32, 0><<<tblocks, 192, smem_t1>>>(x, W1, (__half2*)y1p, n_nodes);
    // G1: h = gather(y1)  (8 lanes/node, 3x LDG.64/edge)
    gather_h32<NWARP, GRP><<<gblocks, NWARP * 32>>>(
        row_ptr, col_idx, p, mu, sg, (const uint2*)y1p, hp, n_nodes);
    // T2: y2 = h * W2  (fp16 padded 128B rows)
    transform_kernel<32, 16, 1><<<tblocks, 192, smem_t2>>>(hp, W2, (__half2*)y2p, n_nodes);
    // G2: out = gather(y2)  (8 lanes/node, 1x LDG.128/edge)
    gather_h16<NWARP, GRP><<<gblocks, NWARP * 32>>>(
        row_ptr, col_idx, p, mu, sg, (const uint4*)y2p, (float*)d_out, n_nodes);
}

// round 8
// speedup vs baseline: 1.1495x; 1.0416x over previous
#include <cuda_runtime.h>
#include <cuda_fp16.h>
#include <cstddef>

// ---------------------------------------------------------------------------
// GMM (MoNet) graph conv — 3-kernel pipeline:
//   T1:   y1[m][k][h] fp16 (unpadded 192B rows)           dense ffma2 GEMM
//   G1T2: h[n] = gather(y1) (smem only), then per-node GEMM y2 = h*W2,
//         y2 stored as padded 128B rows [8 chunks][{k0,k1,k2,pad} half2]
//   G2:   out[n] = gather(y2), 1 LDG.128 per edge-lane (1 line/node)
// ---------------------------------------------------------------------------

#define MAXN 131072
__device__ __half g_y1[MAXN * 96];   // [N][3][32]  unpadded, 192B rows
__device__ __half g_y2[MAXN * 64];   // [N][8 chunks][8 halves], 128B rows

typedef unsigned long long ull;

__device__ __forceinline__ ull pk2(float x, float y) {
    ull r; asm("mov.b64 %0, {%1,%2};" : "=l"(r) : "f"(x), "f"(y)); return r;
}
__device__ __forceinline__ void upk2(ull v, float& x, float& y) {
    asm("mov.b64 {%0,%1}, %2;" : "=f"(x), "=f"(y) : "l"(v));
}
__device__ __forceinline__ void ffma2(ull& d, ull a, ull b) {
    asm("fma.rn.f32x2 %0, %1, %2, %0;" : "+l"(d) : "l"(a), "l"(b));
}

// ======================= T1: dense transform (ffma2 GEMM) ==================
// half2 index = m*NC2 + k*H2 + hp  (unpadded)
template<int KD, int H>
__global__ void __launch_bounds__(192)
transform_kernel(const float* __restrict__ X, const float* __restrict__ W,
                 __half2* __restrict__ Y, int n_nodes)
{
    constexpr int NCOL = 3 * H;
    constexpr int NC2  = NCOL / 2;
    constexpr int NT   = NC2 / 12;
    constexpr int H2   = H / 2;
    constexpr int MT   = 128;
    constexpr int XSTR = MT + 2;

    extern __shared__ float smem[];
    float* Xs = smem;                      // [KD][XSTR]
    float* Ws = smem + KD * XSTR;          // [KD][NCOL]

    const int tid = threadIdx.x;
    const int mt0 = blockIdx.x * MT;

    for (int i = tid; i < KD * NCOL; i += 192) {
        int f = i / NCOL, n = i % NCOL;
        int k = n / H, h = n % H;
        Ws[f * NCOL + n] = W[((size_t)k * KD + f) * H + h];
    }
    for (int i = tid; i < MT * KD; i += 192) {
        int m = i / KD, f = i % KD;
        float v = 0.f;
        if (mt0 + m < n_nodes) v = X[(size_t)(mt0 + m) * KD + f];
        Xs[f * XSTR + m] = v;
    }
    __syncthreads();

    const int tx = tid % 12;
    const int ty = tid / 12;
    const int m0 = ty * 8;

    ull acc[8][NT];
    #pragma unroll
    for (int i = 0; i < 8; i++)
        #pragma unroll
        for (int s = 0; s < NT; s++) acc[i][s] = 0ull;

    for (int f = 0; f < KD; f++) {
        float xm[8];
        #pragma unroll
        for (int i = 0; i < 4; i++) {
            const ull xp = *(const ull*)&Xs[f * XSTR + m0 + 2 * i];
            upk2(xp, xm[2 * i], xm[2 * i + 1]);
        }
        #pragma unroll
        for (int s = 0; s < NT; s++) {
            const ull wp = *(const ull*)&Ws[f * NCOL + 2 * (tx + 12 * s)];
            #pragma unroll
            for (int i = 0; i < 8; i++)
                ffma2(acc[i][s], pk2(xm[i], xm[i]), wp);
        }
    }

    #pragma unroll
    for (int i = 0; i < 8; i++) {
        const int m = mt0 + m0 + i;
        if (m >= n_nodes) break;
        #pragma unroll
        for (int s = 0; s < NT; s++) {
            float v0, v1; upk2(acc[i][s], v0, v1);
            const int j  = tx + 12 * s;
            const int k  = j / H2;
            const int hp = j % H2;
            Y[(size_t)m * NC2 + k * H2 + hp] = __floats2half2_rn(v0, v1);
        }
    }
}

// ============================== gaussians ==================================
#define LOAD_GAUSS_PARAMS()                                                   \
    const float m0_ = mu[0], m1_ = mu[1], m2_ = mu[2],                        \
                m3_ = mu[3], m4_ = mu[4], m5_ = mu[5];                        \
    float s_;                                                                 \
    s_ = sigma[0]; const float i0_ = 1.f/(s_*s_);                             \
    s_ = sigma[1]; const float i1_ = 1.f/(s_*s_);                             \
    s_ = sigma[2]; const float i2_ = 1.f/(s_*s_);                             \
    s_ = sigma[3]; const float i3_ = 1.f/(s_*s_);                             \
    s_ = sigma[4]; const float i4_ = 1.f/(s_*s_);                             \
    s_ = sigma[5]; const float i5_ = 1.f/(s_*s_);

#define GAUSS3(pv, g0, g1, g2) do {                                           \
    float dx_, dy_, q_;                                                       \
    dx_ = (pv).x - m0_; dy_ = (pv).y - m1_;                                   \
    q_ = dx_*dx_*i0_ + dy_*dy_*i1_; g0 = __expf(-0.5f * q_);                  \
    dx_ = (pv).x - m2_; dy_ = (pv).y - m3_;                                   \
    q_ = dx_*dx_*i2_ + dy_*dy_*i3_; g1 = __expf(-0.5f * q_);                  \
    dx_ = (pv).x - m4_; dy_ = (pv).y - m5_;                                   \
    q_ = dx_*dx_*i4_ + dy_*dy_*i5_; g2 = __expf(-0.5f * q_);                  \
} while (0)

// ============== G1 + T2 fused: gather -> h (smem) -> y2 = h*W2 =============
// Gather: 8 lanes/node, 3x LDG.64/edge (unpadded 192B y1 rows).
// GEMM:   24 lanes own one (hp,k) output pair for all 8 group nodes.
template<int NWARP, int GRP>
__global__ void __launch_bounds__(NWARP * 32)
g1t2_kernel(const int* __restrict__ row_ptr, const int* __restrict__ col_idx,
            const float2* __restrict__ p,
            const float* __restrict__ mu, const float* __restrict__ sigma,
            const uint2* __restrict__ y,      // y1: [N][24] uint2
            const float* __restrict__ W2,     // [3][32][16]
            unsigned* __restrict__ y2,        // [N][32] uint (128B rows)
            int n_nodes)
{
    constexpr int CAP = GRP * 16;
    __shared__ float4 stg[NWARP][CAP];
    __shared__ float  hbuf[NWARP][GRP][32];
    __shared__ ull    wp[24 * 33];            // W2 pairs, stride 33 (2-way max)

    const int tid  = threadIdx.x;
    const int lane = tid & 31;
    const int wid  = tid >> 5;

    // Stage W2 pairs: wp[l][f] = (W2[k][f][2hp], W2[k][f][2hp+1]), l=(hp,k)
    for (int i = tid; i < 24 * 32; i += NWARP * 32) {
        const int l = i / 32, f = i % 32;
        const int hp = l / 3, k = l % 3;
        const float* wrow = W2 + ((size_t)k * 32 + f) * 16 + 2 * hp;
        wp[l * 33 + f] = pk2(wrow[0], wrow[1]);
    }
    __syncthreads();

    const int base = (blockIdx.x * NWARP + wid) * GRP;
    if (base >= n_nodes) return;

    LOAD_GAUSS_PARAMS();

    const int ng   = min(GRP, n_nodes - base);
    const int e0   = row_ptr[base];
    const int ecnt = row_ptr[base + ng] - e0;
    const bool fast = (ecnt <= CAP);

    if (fast) {
        for (int j = lane; j < ecnt; j += 32) {
            const int e = e0 + j;
            const int c = col_idx[e];
            const float2 pv = __ldg(p + e);
            float g0, g1, g2; GAUSS3(pv, g0, g1, g2);
            stg[wid][j] = make_float4(g0, g1, g2, __int_as_float(c));
        }
    }
    __syncwarp();

    // ---------------- gather phase: h -> hbuf ----------------
    const int s  = lane >> 3;               // node slot (4 per pass)
    const int hl = lane & 7;

    #pragma unroll
    for (int pi = 0; pi < GRP / 4; pi++) {
        const int n = base + pi * 4 + s;
        const bool valid = (n < n_nodes);
        const int nc  = valid ? n : base;
        const int st  = __ldg(row_ptr + nc);
        const int deg = valid ? (__ldg(row_ptr + nc + 1) - st) : 0;

        ull a[3][2];
        #pragma unroll
        for (int k = 0; k < 3; k++) { a[k][0] = 0ull; a[k][1] = 0ull; }

        if (fast) {
            const float4* sd = &stg[wid][st - e0];
            const bool u16 = __all_sync(0xffffffffu, deg == 16);
            #define G1_BODY(J) do {                                           \
                const float4 ed = sd[(J)];                                    \
                const int c = __float_as_int(ed.w);                           \
                const uint2* yr = y + (size_t)c * 24 + hl;                    \
                const uint2 v0 = __ldg(yr);                                   \
                const uint2 v1 = __ldg(yr + 8);                               \
                const uint2 v2 = __ldg(yr + 16);                              \
                const float2 c00 = __half22float2(*(const __half2*)&v0.x);    \
                const float2 c01 = __half22float2(*(const __half2*)&v0.y);    \
                const float2 c10 = __half22float2(*(const __half2*)&v1.x);    \
                const float2 c11 = __half22float2(*(const __half2*)&v1.y);    \
                const float2 c20 = __half22float2(*(const __half2*)&v2.x);    \
                const float2 c21 = __half22float2(*(const __half2*)&v2.y);    \
                const ull w0 = pk2(ed.x, ed.x);                               \
                const ull w1 = pk2(ed.y, ed.y);                               \
                const ull w2 = pk2(ed.z, ed.z);                               \
                ffma2(a[0][0], w0, pk2(c00.x, c00.y));                        \
                ffma2(a[0][1], w0, pk2(c01.x, c01.y));                        \
                ffma2(a[1][0], w1, pk2(c10.x, c10.y));                        \
                ffma2(a[1][1], w1, pk2(c11.x, c11.y));                        \
                ffma2(a[2][0], w2, pk2(c20.x, c20.y));                        \
                ffma2(a[2][1], w2, pk2(c21.x, c21.y));                        \
            } while (0)
            if (u16) {
                #pragma unroll
                for (int j = 0; j < 16; j++) G1_BODY(j);
            } else {
                const int maxd = __reduce_max_sync(0xffffffffu, deg);
                for (int j = 0; j < maxd; j++)
                    if (j < deg) G1_BODY(j);
            }
            #undef G1_BODY
        } else {
            const int maxd = __reduce_max_sync(0xffffffffu, deg);
            for (int j = 0; j < maxd; j++) {
                if (j < deg) {
                    const int e = st + j;
                    const int c = __ldg(col_idx + e);
                    const float2 pv = __ldg(p + e);
                    float g0, g1, g2; GAUSS3(pv, g0, g1, g2);
                    const uint2* yr = y + (size_t)c * 24 + hl;
                    const uint2 v0 = __ldg(yr);
                    const uint2 v1 = __ldg(yr + 8);
                    const uint2 v2 = __ldg(yr + 16);
                    const float2 c00 = __half22float2(*(const __half2*)&v0.x);
                    const float2 c01 = __half22float2(*(const __half2*)&v0.y);
                    const float2 c10 = __half22float2(*(const __half2*)&v1.x);
                    const float2 c11 = __half22float2(*(const __half2*)&v1.y);
                    const float2 c20 = __half22float2(*(const __half2*)&v2.x);
                    const float2 c21 = __half22float2(*(const __half2*)&v2.y);
                    ffma2(a[0][0], pk2(g0, g0), pk2(c00.x, c00.y));
                    ffma2(a[0][1], pk2(g0, g0), pk2(c01.x, c01.y));
                    ffma2(a[1][0], pk2(g1, g1), pk2(c10.x, c10.y));
                    ffma2(a[1][1], pk2(g1, g1), pk2(c11.x, c11.y));
                    ffma2(a[2][0], pk2(g2, g2), pk2(c20.x, c20.y));
                    ffma2(a[2][1], pk2(g2, g2), pk2(c21.x, c21.y));
                }
            }
        }

        // h[n][4hl..4hl+3] -> smem
        float p00, p01, p10, p11, q00, q01, q10, q11, r00, r01, r10, r11;
        upk2(a[0][0], p00, p01); upk2(a[0][1], p10, p11);
        upk2(a[1][0], q00, q01); upk2(a[1][1], q10, q11);
        upk2(a[2][0], r00, r01); upk2(a[2][1], r10, r11);
        float4 o;
        o.x = p00 + q00 + r00;
        o.y = p01 + q01 + r01;
        o.z = p10 + q10 + r10;
        o.w = p11 + q11 + r11;
        *(float4*)&hbuf[wid][pi * 4 + s][4 * hl] = o;
    }
    __syncwarp();

    // ---------------- fused T2: y2[g] = h[g] * W2 ----------------
    const int wl = (lane < 24) ? lane : 0;
    const ull* wcol = wp + wl * 33;

    ull acc[GRP];
    #pragma unroll
    for (int g = 0; g < GRP; g++) acc[g] = 0ull;

    #pragma unroll
    for (int fc = 0; fc < 8; fc++) {
        ull wr[4];
        #pragma unroll
        for (int f4 = 0; f4 < 4; f4++) wr[f4] = wcol[fc * 4 + f4];
        #pragma unroll
        for (int g = 0; g < GRP; g++) {
            const float4 hv = *(const float4*)&hbuf[wid][g][fc * 4];
            ffma2(acc[g], pk2(hv.x, hv.x), wr[0]);
            ffma2(acc[g], pk2(hv.y, hv.y), wr[1]);
            ffma2(acc[g], pk2(hv.z, hv.z), wr[2]);
            ffma2(acc[g], pk2(hv.w, hv.w), wr[3]);
        }
    }

    const int oidx = (lane / 3) * 4 + (lane % 3);   // chunk hp, slot k
    #pragma unroll
    for (int g = 0; g < GRP; g++) {
        const int n = base + g;
        if (lane < 24 && n < n_nodes) {
            float lo, hi; upk2(acc[g], lo, hi);
            const __half2 hv = __floats2half2_rn(lo, hi);
            y2[(size_t)n * 32 + oidx] = *(const unsigned*)&hv;
        }
    }
}

// ---- G2: H=16, padded 128B rows; 8 lanes/node, 1x LDG.128 per edge --------
template<int NWARP, int GRP>
__global__ void __launch_bounds__(NWARP * 32)
gather_h16(const int* __restrict__ row_ptr, const int* __restrict__ col_idx,
           const float2* __restrict__ p,
           const float* __restrict__ mu, const float* __restrict__ sigma,
           const uint4* __restrict__ y,     // [N][8] 16B chunks
           float* __restrict__ out,         // [N][16] f32
           int n_nodes)
{
    constexpr int CAP = GRP * 16;
    __shared__ float4 stg[NWARP][CAP];

    const int lane = threadIdx.x & 31;
    const int wid  = threadIdx.x >> 5;
    const int s    = lane >> 3;
    const int hl   = lane & 7;
    const int base = (blockIdx.x * NWARP + wid) * GRP;
    if (base >= n_nodes) return;

    LOAD_GAUSS_PARAMS();

    const int ng   = min(GRP, n_nodes - base);
    const int e0   = row_ptr[base];
    const int ecnt = row_ptr[base + ng] - e0;
    const bool fast = (ecnt <= CAP);

    if (fast) {
        for (int j = lane; j < ecnt; j += 32) {
            const int e = e0 + j;
            const int c = col_idx[e];
            const float2 pv = __ldg(p + e);
            float g0, g1, g2; GAUSS3(pv, g0, g1, g2);
            stg[wid][j] = make_float4(g0, g1, g2, __int_as_float(c));
        }
    }
    __syncwarp();

    #pragma unroll
    for (int pi = 0; pi < GRP / 4; pi++) {
        const int n = base + pi * 4 + s;
        const bool valid = (n < n_nodes);
        const int nc  = valid ? n : base;
        const int st  = __ldg(row_ptr + nc);
        const int deg = valid ? (__ldg(row_ptr + nc + 1) - st) : 0;

        ull a0 = 0ull, a1 = 0ull, a2 = 0ull;

        if (fast) {
            const float4* sd = &stg[wid][st - e0];
            const bool u16 = __all_sync(0xffffffffu, deg == 16);
            #define G2_BODY(J) do {                                           \
                const float4 ed = sd[(J)];                                    \
                const int c = __float_as_int(ed.w);                           \
                const uint4 v = __ldg(y + (size_t)c * 8 + hl);                \
                const float2 f0 = __half22float2(*(const __half2*)&v.x);      \
                const float2 f1 = __half22float2(*(const __half2*)&v.y);      \
                const float2 f2 = __half22float2(*(const __half2*)&v.z);      \
                ffma2(a0, pk2(ed.x, ed.x), pk2(f0.x, f0.y));                  \
                ffma2(a1, pk2(ed.y, ed.y), pk2(f1.x, f1.y));                  \
                ffma2(a2, pk2(ed.z, ed.z), pk2(f2.x, f2.y));                  \
            } while (0)
            if (u16) {
                #pragma unroll
                for (int j = 0; j < 16; j++) G2_BODY(j);
            } else {
                const int maxd = __reduce_max_sync(0xffffffffu, deg);
                for (int j = 0; j < maxd; j++)
                    if (j < deg) G2_BODY(j);
            }
            #undef G2_BODY
        } else {
            const int maxd = __reduce_max_sync(0xffffffffu, deg);
            for (int j = 0; j < maxd; j++) {
                if (j < deg) {
                    const int e = st + j;
                    const int c = __ldg(col_idx + e);
                    const float2 pv = __ldg(p + e);
                    float g0, g1, g2; GAUSS3(pv, g0, g1, g2);
                    const uint4 v = __ldg(y + (size_t)c * 8 + hl);
                    const float2 f0 = __half22float2(*(const __half2*)&v.x);
                    const float2 f1 = __half22float2(*(const __half2*)&v.y);
                    const float2 f2 = __half22float2(*(const __half2*)&v.z);
                    ffma2(a0, pk2(g0, g0), pk2(f0.x, f0.y));
                    ffma2(a1, pk2(g1, g1), pk2(f1.x, f1.y));
                    ffma2(a2, pk2(g2, g2), pk2(f2.x, f2.y));
                }
            }
        }

        if (valid) {
            float x0, x1, y0v, y1v, z0, z1;
            upk2(a0, x0, x1); upk2(a1, y0v, y1v); upk2(a2, z0, z1);
            float2 o = make_float2(x0 + y0v + z0, x1 + y1v + z1);
            *(float2*)(out + (size_t)n * 16 + 2 * hl) = o;
        }
    }
}

// =============================== launch ====================================
extern "C" void kernel_launch(void* const* d_in, const int* in_sizes, int n_in,
                              void* d_out, int out_size)
{
    const int*    row_ptr = (const int*)d_in[0];    // int32 (JAX x64 disabled)
    const int*    col_idx = (const int*)d_in[1];
    const float*  x       = (const float*)d_in[2];
    const float2* p       = (const float2*)d_in[3];
    const float*  mu      = (const float*)d_in[4];
    const float*  sg      = (const float*)d_in[5];
    const float*  W1      = (const float*)d_in[6];
    const float*  W2      = (const float*)d_in[7];

    const int n_nodes = in_sizes[0] - 1;

    void *y1p, *y2p;
    cudaGetSymbolAddress(&y1p, g_y1);
    cudaGetSymbolAddress(&y2p, g_y2);

    constexpr int NWARP = 8;
    constexpr int GRP   = 8;
    const int gblocks = (n_nodes + NWARP * GRP - 1) / (NWARP * GRP);
    const int tblocks = (n_nodes + 127) / 128;

    constexpr size_t smem_t1 = (64 * 130 + 64 * 96) * sizeof(float);  // 57.9KB
    cudaFuncSetAttribute(transform_kernel<64, 32>,
                         cudaFuncAttributeMaxDynamicSharedMemorySize, (int)smem_t1);

    // T1: y1 = x * W1  (fp16 unpadded [3][16]half2 rows)
    transform_kernel<64, 32><<<tblocks, 192, smem_t1>>>(x, W1, (__half2*)y1p, n_nodes);
    // G1+T2: h = gather(y1) in smem; y2 = h*W2 (padded 128B rows)
    g1t2_kernel<NWARP, GRP><<<gblocks, NWARP * 32>>>(
        row_ptr, col_idx, p, mu, sg, (const uint2*)y1p, W2,
        (unsigned*)y2p, n_nodes);
    // G2: out = gather(y2)  (8 lanes/node, 1x LDG.128/edge)
    gather_h16<NWARP, GRP><<<gblocks, NWARP * 32>>>(
        row_ptr, col_idx, p, mu, sg, (const uint4*)y2p, (float*)d_out, n_nodes);
}

// round 9
// speedup vs baseline: 1.1968x; 1.0411x over previous
#include <cuda_runtime.h>
#include <cuda_fp16.h>
#include <cstddef>

// ---------------------------------------------------------------------------
// GMM (MoNet) graph conv — 3-kernel pipeline:
//   T1:   y1[m][k][h] fp16 (unpadded 192B rows)           dense ffma2 GEMM
//   G1T2: h[n] = gather(y1) (smem only), then per-node GEMM y2 = h*W2,
//         y2 stored as padded 128B rows [8 chunks][{k0,k1,k2,pad} half2]
//   G2:   out[n] = gather(y2), 1 LDG.128 per edge-lane (1 line/node)
// ---------------------------------------------------------------------------

#define MAXN 131072
__device__ __half g_y1[MAXN * 96];   // [N][3][32]  unpadded, 192B rows
__device__ __half g_y2[MAXN * 64];   // [N][8 chunks][8 halves], 128B rows

typedef unsigned long long ull;

__device__ __forceinline__ ull pk2(float x, float y) {
    ull r; asm("mov.b64 %0, {%1,%2};" : "=l"(r) : "f"(x), "f"(y)); return r;
}
__device__ __forceinline__ void upk2(ull v, float& x, float& y) {
    asm("mov.b64 {%0,%1}, %2;" : "=f"(x), "=f"(y) : "l"(v));
}
__device__ __forceinline__ void ffma2(ull& d, ull a, ull b) {
    asm("fma.rn.f32x2 %0, %1, %2, %0;" : "+l"(d) : "l"(a), "l"(b));
}

// ======================= T1: dense transform (ffma2 GEMM) ==================
// MT=64 m-tile, 192 thr = 12(tx,n) x 16(ty,m), 4 m-rows x 4 n-pairs/thread.
// smem 41.5KB -> 5 CTA/SM; __launch_bounds__(192,5) pins regs <= 68.
template<int KD, int H>
__global__ void __launch_bounds__(192, 5)
transform_kernel(const float* __restrict__ X, const float* __restrict__ W,
                 __half2* __restrict__ Y, int n_nodes)
{
    constexpr int NCOL = 3 * H;
    constexpr int NC2  = NCOL / 2;
    constexpr int NT   = NC2 / 12;         // 4 for H=32
    constexpr int H2   = H / 2;
    constexpr int MT   = 64;
    constexpr int XSTR = MT + 2;

    extern __shared__ float smem[];
    float* Xs = smem;                      // [KD][XSTR]
    float* Ws = smem + KD * XSTR;          // [KD][NCOL]

    const int tid = threadIdx.x;
    const int mt0 = blockIdx.x * MT;

    for (int i = tid; i < KD * NCOL; i += 192) {
        int f = i / NCOL, n = i % NCOL;
        int k = n / H, h = n % H;
        Ws[f * NCOL + n] = W[((size_t)k * KD + f) * H + h];
    }
    for (int i = tid; i < MT * KD; i += 192) {
        int m = i / KD, f = i % KD;
        float v = 0.f;
        if (mt0 + m < n_nodes) v = X[(size_t)(mt0 + m) * KD + f];
        Xs[f * XSTR + m] = v;
    }
    __syncthreads();

    const int tx = tid % 12;
    const int ty = tid / 12;               // 0..15
    const int m0 = ty * 4;

    ull acc[4][NT];                        // [m-row][n-pair]
    #pragma unroll
    for (int i = 0; i < 4; i++)
        #pragma unroll
        for (int s = 0; s < NT; s++) acc[i][s] = 0ull;

    for (int f = 0; f < KD; f++) {
        float xm[4];
        {
            const ull xa = *(const ull*)&Xs[f * XSTR + m0];
            const ull xb = *(const ull*)&Xs[f * XSTR + m0 + 2];
            upk2(xa, xm[0], xm[1]);
            upk2(xb, xm[2], xm[3]);
        }
        ull xp[4];
        #pragma unroll
        for (int i = 0; i < 4; i++) xp[i] = pk2(xm[i], xm[i]);

        #pragma unroll
        for (int s = 0; s < NT; s++) {
            const ull wp = *(const ull*)&Ws[f * NCOL + 2 * (tx + 12 * s)];
            #pragma unroll
            for (int i = 0; i < 4; i++)
                ffma2(acc[i][s], xp[i], wp);
        }
    }

    #pragma unroll
    for (int i = 0; i < 4; i++) {
        const int m = mt0 + m0 + i;
        if (m >= n_nodes) break;
        #pragma unroll
        for (int s = 0; s < NT; s++) {
            float v0, v1; upk2(acc[i][s], v0, v1);
            const int j  = tx + 12 * s;
            const int k  = j / H2;
            const int hp = j % H2;
            Y[(size_t)m * NC2 + k * H2 + hp] = __floats2half2_rn(v0, v1);
        }
    }
}

// ============================== gaussians ==================================
#define LOAD_GAUSS_PARAMS()                                                   \
    const float m0_ = mu[0], m1_ = mu[1], m2_ = mu[2],                        \
                m3_ = mu[3], m4_ = mu[4], m5_ = mu[5];                        \
    float s_;                                                                 \
    s_ = sigma[0]; const float i0_ = 1.f/(s_*s_);                             \
    s_ = sigma[1]; const float i1_ = 1.f/(s_*s_);                             \
    s_ = sigma[2]; const float i2_ = 1.f/(s_*s_);                             \
    s_ = sigma[3]; const float i3_ = 1.f/(s_*s_);                             \
    s_ = sigma[4]; const float i4_ = 1.f/(s_*s_);                             \
    s_ = sigma[5]; const float i5_ = 1.f/(s_*s_);

#define GAUSS3(pv, g0, g1, g2) do {                                           \
    float dx_, dy_, q_;                                                       \
    dx_ = (pv).x - m0_; dy_ = (pv).y - m1_;                                   \
    q_ = dx_*dx_*i0_ + dy_*dy_*i1_; g0 = __expf(-0.5f * q_);                  \
    dx_ = (pv).x - m2_; dy_ = (pv).y - m3_;                                   \
    q_ = dx_*dx_*i2_ + dy_*dy_*i3_; g1 = __expf(-0.5f * q_);                  \
    dx_ = (pv).x - m4_; dy_ = (pv).y - m5_;                                   \
    q_ = dx_*dx_*i4_ + dy_*dy_*i5_; g2 = __expf(-0.5f * q_);                  \
} while (0)

// ============== G1 + T2 fused: gather -> h (smem) -> y2 = h*W2 =============
template<int NWARP, int GRP>
__global__ void __launch_bounds__(NWARP * 32)
g1t2_kernel(const int* __restrict__ row_ptr, const int* __restrict__ col_idx,
            const float2* __restrict__ p,
            const float* __restrict__ mu, const float* __restrict__ sigma,
            const uint2* __restrict__ y,      // y1: [N][24] uint2
            const float* __restrict__ W2,     // [3][32][16]
            unsigned* __restrict__ y2,        // [N][32] uint (128B rows)
            int n_nodes)
{
    constexpr int CAP = GRP * 16;
    __shared__ float4 stg[NWARP][CAP];
    __shared__ float  hbuf[NWARP][GRP][32];
    __shared__ ull    wp[24 * 33];            // W2 pairs, stride 33

    const int tid  = threadIdx.x;
    const int lane = tid & 31;
    const int wid  = tid >> 5;

    for (int i = tid; i < 24 * 32; i += NWARP * 32) {
        const int l = i / 32, f = i % 32;
        const int hp = l / 3, k = l % 3;
        const float* wrow = W2 + ((size_t)k * 32 + f) * 16 + 2 * hp;
        wp[l * 33 + f] = pk2(wrow[0], wrow[1]);
    }
    __syncthreads();

    const int base = (blockIdx.x * NWARP + wid) * GRP;
    if (base >= n_nodes) return;

    LOAD_GAUSS_PARAMS();

    const int ng   = min(GRP, n_nodes - base);
    const int e0   = row_ptr[base];
    const int ecnt = row_ptr[base + ng] - e0;
    const bool fast = (ecnt <= CAP);

    if (fast) {
        for (int j = lane; j < ecnt; j += 32) {
            const int e = e0 + j;
            const int c = col_idx[e];
            const float2 pv = __ldg(p + e);
            float g0, g1, g2; GAUSS3(pv, g0, g1, g2);
            stg[wid][j] = make_float4(g0, g1, g2, __int_as_float(c));
        }
    }
    __syncwarp();

    const int s  = lane >> 3;
    const int hl = lane & 7;

    #pragma unroll
    for (int pi = 0; pi < GRP / 4; pi++) {
        const int n = base + pi * 4 + s;
        const bool valid = (n < n_nodes);
        const int nc  = valid ? n : base;
        const int st  = __ldg(row_ptr + nc);
        const int deg = valid ? (__ldg(row_ptr + nc + 1) - st) : 0;

        ull a[3][2];
        #pragma unroll
        for (int k = 0; k < 3; k++) { a[k][0] = 0ull; a[k][1] = 0ull; }

        if (fast) {
            const float4* sd = &stg[wid][st - e0];
            const bool u16 = __all_sync(0xffffffffu, deg == 16);
            #define G1_BODY(J) do {                                           \
                const float4 ed = sd[(J)];                                    \
                const int c = __float_as_int(ed.w);                           \
                const uint2* yr = y + (size_t)c * 24 + hl;                    \
                const uint2 v0 = __ldg(yr);                                   \
                const uint2 v1 = __ldg(yr + 8);                               \
                const uint2 v2 = __ldg(yr + 16);                              \
                const float2 c00 = __half22float2(*(const __half2*)&v0.x);    \
                const float2 c01 = __half22float2(*(const __half2*)&v0.y);    \
                const float2 c10 = __half22float2(*(const __half2*)&v1.x);    \
                const float2 c11 = __half22float2(*(const __half2*)&v1.y);    \
                const float2 c20 = __half22float2(*(const __half2*)&v2.x);    \
                const float2 c21 = __half22float2(*(const __half2*)&v2.y);    \
                const ull w0 = pk2(ed.x, ed.x);                               \
                const ull w1 = pk2(ed.y, ed.y);                               \
                const ull w2 = pk2(ed.z, ed.z);                               \
                ffma2(a[0][0], w0, pk2(c00.x, c00.y));                        \
                ffma2(a[0][1], w0, pk2(c01.x, c01.y));                        \
                ffma2(a[1][0], w1, pk2(c10.x, c10.y));                        \
                ffma2(a[1][1], w1, pk2(c11.x, c11.y));                        \
                ffma2(a[2][0], w2, pk2(c20.x, c20.y));                        \
                ffma2(a[2][1], w2, pk2(c21.x, c21.y));                        \
            } while (0)
            if (u16) {
                #pragma unroll
                for (int j = 0; j < 16; j++) G1_BODY(j);
            } else {
                const int maxd = __reduce_max_sync(0xffffffffu, deg);
                for (int j = 0; j < maxd; j++)
                    if (j < deg) G1_BODY(j);
            }
            #undef G1_BODY
        } else {
            const int maxd = __reduce_max_sync(0xffffffffu, deg);
            for (int j = 0; j < maxd; j++) {
                if (j < deg) {
                    const int e = st + j;
                    const int c = __ldg(col_idx + e);
                    const float2 pv = __ldg(p + e);
                    float g0, g1, g2; GAUSS3(pv, g0, g1, g2);
                    const uint2* yr = y + (size_t)c * 24 + hl;
                    const uint2 v0 = __ldg(yr);
                    const uint2 v1 = __ldg(yr + 8);
                    const uint2 v2 = __ldg(yr + 16);
                    const float2 c00 = __half22float2(*(const __half2*)&v0.x);
                    const float2 c01 = __half22float2(*(const __half2*)&v0.y);
                    const float2 c10 = __half22float2(*(const __half2*)&v1.x);
                    const float2 c11 = __half22float2(*(const __half2*)&v1.y);
                    const float2 c20 = __half22float2(*(const __half2*)&v2.x);
                    const float2 c21 = __half22float2(*(const __half2*)&v2.y);
                    ffma2(a[0][0], pk2(g0, g0), pk2(c00.x, c00.y));
                    ffma2(a[0][1], pk2(g0, g0), pk2(c01.x, c01.y));
                    ffma2(a[1][0], pk2(g1, g1), pk2(c10.x, c10.y));
                    ffma2(a[1][1], pk2(g1, g1), pk2(c11.x, c11.y));
                    ffma2(a[2][0], pk2(g2, g2), pk2(c20.x, c20.y));
                    ffma2(a[2][1], pk2(g2, g2), pk2(c21.x, c21.y));
                }
            }
        }

        float p00, p01, p10, p11, q00, q01, q10, q11, r00, r01, r10, r11;
        upk2(a[0][0], p00, p01); upk2(a[0][1], p10, p11);
        upk2(a[1][0], q00, q01); upk2(a[1][1], q10, q11);
        upk2(a[2][0], r00, r01); upk2(a[2][1], r10, r11);
        float4 o;
        o.x = p00 + q00 + r00;
        o.y = p01 + q01 + r01;
        o.z = p10 + q10 + r10;
        o.w = p11 + q11 + r11;
        *(float4*)&hbuf[wid][pi * 4 + s][4 * hl] = o;
    }
    __syncwarp();

    // fused T2: y2[g] = h[g] * W2
    const int wl = (lane < 24) ? lane : 0;
    const ull* wcol = wp + wl * 33;

    ull acc[GRP];
    #pragma unroll
    for (int g = 0; g < GRP; g++) acc[g] = 0ull;

    #pragma unroll
    for (int fc = 0; fc < 8; fc++) {
        ull wr[4];
        #pragma unroll
        for (int f4 = 0; f4 < 4; f4++) wr[f4] = wcol[fc * 4 + f4];
        #pragma unroll
        for (int g = 0; g < GRP; g++) {
            const float4 hv = *(const float4*)&hbuf[wid][g][fc * 4];
            ffma2(acc[g], pk2(hv.x, hv.x), wr[0]);
            ffma2(acc[g], pk2(hv.y, hv.y), wr[1]);
            ffma2(acc[g], pk2(hv.z, hv.z), wr[2]);
            ffma2(acc[g], pk2(hv.w, hv.w), wr[3]);
        }
    }

    const int oidx = (lane / 3) * 4 + (lane % 3);
    #pragma unroll
    for (int g = 0; g < GRP; g++) {
        const int n = base + g;
        if (lane < 24 && n < n_nodes) {
            float lo, hi; upk2(acc[g], lo, hi);
            const __half2 hv = __floats2half2_rn(lo, hi);
            y2[(size_t)n * 32 + oidx] = *(const unsigned*)&hv;
        }
    }
}

// ---- G2: H=16, padded 128B rows; 8 lanes/node, 1x LDG.128 per edge --------
template<int NWARP, int GRP>
__global__ void __launch_bounds__(NWARP * 32)
gather_h16(const int* __restrict__ row_ptr, const int* __restrict__ col_idx,
           const float2* __restrict__ p,
           const float* __restrict__ mu, const float* __restrict__ sigma,
           const uint4* __restrict__ y,     // [N][8] 16B chunks
           float* __restrict__ out,         // [N][16] f32
           int n_nodes)
{
    constexpr int CAP = GRP * 16;
    __shared__ float4 stg[NWARP][CAP];

    const int lane = threadIdx.x & 31;
    const int wid  = threadIdx.x >> 5;
    const int s    = lane >> 3;
    const int hl   = lane & 7;
    const int base = (blockIdx.x * NWARP + wid) * GRP;
    if (base >= n_nodes) return;

    LOAD_GAUSS_PARAMS();

    const int ng   = min(GRP, n_nodes - base);
    const int e0   = row_ptr[base];
    const int ecnt = row_ptr[base + ng] - e0;
    const bool fast = (ecnt <= CAP);

    if (fast) {
        for (int j = lane; j < ecnt; j += 32) {
            const int e = e0 + j;
            const int c = col_idx[e];
            const float2 pv = __ldg(p + e);
            float g0, g1, g2; GAUSS3(pv, g0, g1, g2);
            stg[wid][j] = make_float4(g0, g1, g2, __int_as_float(c));
        }
    }
    __syncwarp();

    #pragma unroll
    for (int pi = 0; pi < GRP / 4; pi++) {
        const int n = base + pi * 4 + s;
        const bool valid = (n < n_nodes);
        const int nc  = valid ? n : base;
        const int st  = __ldg(row_ptr + nc);
        const int deg = valid ? (__ldg(row_ptr + nc + 1) - st) : 0;

        ull a0 = 0ull, a1 = 0ull, a2 = 0ull;

        if (fast) {
            const float4* sd = &stg[wid][st - e0];
            const bool u16 = __all_sync(0xffffffffu, deg == 16);
            #define G2_BODY(J) do {                                           \
                const float4 ed = sd[(J)];                                    \
                const int c = __float_as_int(ed.w);                           \
                const uint4 v = __ldg(y + (size_t)c * 8 + hl);                \
                const float2 f0 = __half22float2(*(const __half2*)&v.x);      \
                const float2 f1 = __half22float2(*(const __half2*)&v.y);      \
                const float2 f2 = __half22float2(*(const __half2*)&v.z);      \
                ffma2(a0, pk2(ed.x, ed.x), pk2(f0.x, f0.y));                  \
                ffma2(a1, pk2(ed.y, ed.y), pk2(f1.x, f1.y));                  \
                ffma2(a2, pk2(ed.z, ed.z), pk2(f2.x, f2.y));                  \
            } while (0)
            if (u16) {
                #pragma unroll
                for (int j = 0; j < 16; j++) G2_BODY(j);
            } else {
                const int maxd = __reduce_max_sync(0xffffffffu, deg);
                for (int j = 0; j < maxd; j++)
                    if (j < deg) G2_BODY(j);
            }
            #undef G2_BODY
        } else {
            const int maxd = __reduce_max_sync(0xffffffffu, deg);
            for (int j = 0; j < maxd; j++) {
                if (j < deg) {
                    const int e = st + j;
                    const int c = __ldg(col_idx + e);
                    const float2 pv = __ldg(p + e);
                    float g0, g1, g2; GAUSS3(pv, g0, g1, g2);
                    const uint4 v = __ldg(y + (size_t)c * 8 + hl);
                    const float2 f0 = __half22float2(*(const __half2*)&v.x);
                    const float2 f1 = __half22float2(*(const __half2*)&v.y);
                    const float2 f2 = __half22float2(*(const __half2*)&v.z);
                    ffma2(a0, pk2(g0, g0), pk2(f0.x, f0.y));
                    ffma2(a1, pk2(g1, g1), pk2(f1.x, f1.y));
                    ffma2(a2, pk2(g2, g2), pk2(f2.x, f2.y));
                }
            }
        }

        if (valid) {
            float x0, x1, y0v, y1v, z0, z1;
            upk2(a0, x0, x1); upk2(a1, y0v, y1v); upk2(a2, z0, z1);
            float2 o = make_float2(x0 + y0v + z0, x1 + y1v + z1);
            *(float2*)(out + (size_t)n * 16 + 2 * hl) = o;
        }
    }
}

// =============================== launch ====================================
extern "C" void kernel_launch(void* const* d_in, const int* in_sizes, int n_in,
                              void* d_out, int out_size)
{
    const int*    row_ptr = (const int*)d_in[0];    // int32 (JAX x64 disabled)
    const int*    col_idx = (const int*)d_in[1];
    const float*  x       = (const float*)d_in[2];
    const float2* p       = (const float2*)d_in[3];
    const float*  mu      = (const float*)d_in[4];
    const float*  sg      = (const float*)d_in[5];
    const float*  W1      = (const float*)d_in[6];
    const float*  W2      = (const float*)d_in[7];

    const int n_nodes = in_sizes[0] - 1;

    void *y1p, *y2p;
    cudaGetSymbolAddress(&y1p, g_y1);
    cudaGetSymbolAddress(&y2p, g_y2);

    constexpr int NWARP = 8;
    constexpr int GRP   = 8;
    const int gblocks = (n_nodes + NWARP * GRP - 1) / (NWARP * GRP);
    const int tblocks = (n_nodes + 63) / 64;

    constexpr size_t smem_t1 = (64 * 66 + 64 * 96) * sizeof(float);   // 41.5KB
    cudaFuncSetAttribute(transform_kernel<64, 32>,
                         cudaFuncAttributeMaxDynamicSharedMemorySize, (int)smem_t1);

    // T1: y1 = x * W1  (fp16 unpadded [3][16]half2 rows)
    transform_kernel<64, 32><<<tblocks, 192, smem_t1>>>(x, W1, (__half2*)y1p, n_nodes);
    // G1+T2: h = gather(y1) in smem; y2 = h*W2 (padded 128B rows)
    g1t2_kernel<NWARP, GRP><<<gblocks, NWARP * 32>>>(
        row_ptr, col_idx, p, mu, sg, (const uint2*)y1p, W2,
        (unsigned*)y2p, n_nodes);
    // G2: out = gather(y2)  (8 lanes/node, 1x LDG.128/edge)
    gather_h16<NWARP, GRP><<<gblocks, NWARP * 32>>>(
        row_ptr, col_idx, p, mu, sg, (const uint4*)y2p, (float*)d_out, n_nodes);
}